// round 3
// baseline (speedup 1.0000x reference)
#include <cuda_runtime.h>
#include <cstdint>

// Problem constants (fixed by the reference)
#define BB 32
#define QQ 900
#define CC 92
#define BIGV 100000000.0f
#define TI 20          // i-rows per block (900 % 20 == 0 -> 45 blocks in x)
#define J4 (QQ / 4)    // 225 float4 groups per output row

// Scratch for softmax probabilities: [B, Q, C] fp32 (~10.6 MB).
__device__ float g_probs[BB * QQ * CC];

// ---------------------------------------------------------------------------
// Kernel 1: row softmax. One warp per (b,i) row of 92 logits.
// Lane l covers columns l, l+32, l+64 (l+64 valid only for l < 28).
// ---------------------------------------------------------------------------
__global__ void softmax_rows_kernel(const float* __restrict__ logits) {
    int gwarp = (blockIdx.x * blockDim.x + threadIdx.x) >> 5;
    int lane  = threadIdx.x & 31;
    if (gwarp >= BB * QQ) return;

    const float* in = logits + (size_t)gwarp * CC;
    float v0 = in[lane];
    float v1 = in[lane + 32];
    bool has2 = lane < (CC - 64);          // lane < 28
    float v2 = has2 ? in[lane + 64] : -1e30f;

    float m = fmaxf(fmaxf(v0, v1), v2);
    #pragma unroll
    for (int o = 16; o > 0; o >>= 1)
        m = fmaxf(m, __shfl_xor_sync(0xFFFFFFFFu, m, o));

    float e0 = __expf(v0 - m);
    float e1 = __expf(v1 - m);
    float e2 = has2 ? __expf(v2 - m) : 0.0f;
    float s = e0 + e1 + e2;
    #pragma unroll
    for (int o = 16; o > 0; o >>= 1)
        s += __shfl_xor_sync(0xFFFFFFFFu, s, o);

    float inv = __fdividef(1.0f, s);
    float* outp = g_probs + (size_t)gwarp * CC;
    outp[lane]      = e0 * inv;
    outp[lane + 32] = e1 * inv;
    if (has2) outp[lane + 64] = e2 * inv;
}

// ---------------------------------------------------------------------------
// Kernel 2: cost matrix. Block = (i-tile of TI rows, batch b).
// Each thread owns 4 consecutive j and emits TI float4 (STG.128) stores.
// ---------------------------------------------------------------------------
__global__ __launch_bounds__(256)
void cost_kernel(const float* __restrict__ pred_boxes,
                 const float* __restrict__ boxes,
                 const float* __restrict__ area,
                 const int*   __restrict__ labels,
                 float* __restrict__ out) {
    const int b  = blockIdx.y;
    const int i0 = blockIdx.x * TI;
    const int tid = threadIdx.x;

    __shared__ float  s_prob[TI][CC];   // softmax rows for the i-tile
    __shared__ float4 s_c[TI];          // pred box cxcywh
    __shared__ float4 s_x[TI];          // pred box xyxy
    __shared__ float  s_a1[TI];         // pred box area (w*h)

    // Load TI softmax rows into shared
    for (int k = tid; k < TI * CC; k += 256) {
        int ii = k / CC;
        int c  = k - ii * CC;
        s_prob[ii][c] = g_probs[((size_t)(b * QQ + i0 + ii)) * CC + c];
    }
    // Load + precompute per-i box data
    if (tid < TI) {
        float4 pb = reinterpret_cast<const float4*>(pred_boxes)[b * QQ + i0 + tid];
        s_c[tid] = pb;
        s_x[tid] = make_float4(pb.x - 0.5f * pb.z, pb.y - 0.5f * pb.w,
                               pb.x + 0.5f * pb.z, pb.y + 0.5f * pb.w);
        s_a1[tid] = pb.z * pb.w;
    }
    __syncthreads();

    if (tid >= J4) return;              // 225 active threads cover j=0..899
    const int j0 = tid * 4;

    // Per-j precomputes for 4 consecutive j
    float4 gb[4];
    float gx0[4], gy0[4], gx1[4], gy1[4], a2[4], prV[4];
    int   lab[4];
    #pragma unroll
    for (int t = 0; t < 4; t++) {
        gb[t] = reinterpret_cast<const float4*>(boxes)[b * QQ + j0 + t];
        lab[t] = labels[b * QQ + j0 + t];
        prV[t] = area[b * QQ + j0 + t];
        gx0[t] = gb[t].x - 0.5f * gb[t].z; gy0[t] = gb[t].y - 0.5f * gb[t].w;
        gx1[t] = gb[t].x + 0.5f * gb[t].z; gy1[t] = gb[t].y + 0.5f * gb[t].w;
        a2[t]  = gb[t].z * gb[t].w;
    }

    float* obase = out + ((size_t)(b * QQ + i0)) * QQ + j0;

    #pragma unroll 4
    for (int ii = 0; ii < TI; ii++) {
        float4 pc = s_c[ii];
        float4 px = s_x[ii];
        float  a1 = s_a1[ii];
        float4 res;
        float* r = &res.x;
        #pragma unroll
        for (int t = 0; t < 4; t++) {
            float cb = 0.25f * (fabsf(pc.x - gb[t].x) + fabsf(pc.y - gb[t].y) +
                                fabsf(pc.z - gb[t].z) + fabsf(pc.w - gb[t].w));
            float iw = fminf(px.z, gx1[t]) - fmaxf(px.x, gx0[t]); iw = fmaxf(iw, 0.0f);
            float ih = fminf(px.w, gy1[t]) - fmaxf(px.y, gy0[t]); ih = fmaxf(ih, 0.0f);
            float inter = iw * ih;
            float uni   = a1 + a2[t] - inter;
            float ew = fmaxf(px.z, gx1[t]) - fminf(px.x, gx0[t]); ew = fmaxf(ew, 0.0f);
            float eh = fmaxf(px.w, gy1[t]) - fminf(px.y, gy0[t]); eh = fmaxf(eh, 0.0f);
            float enc = ew * eh;
            float giou = __fdividef(inter, uni) - __fdividef(enc - uni, enc);
            float cost = cb - s_prob[ii][lab[t]] - giou;
            r[t] = (prV[t] > 0.0f) ? cost : BIGV;
        }
        reinterpret_cast<float4*>(obase + (size_t)ii * QQ)[0] = res;
    }
}

extern "C" void kernel_launch(void* const* d_in, const int* in_sizes, int n_in,
                              void* d_out, int out_size) {
    const float* pred_logits = (const float*)d_in[0];  // [B,Q,C]
    const float* pred_boxes  = (const float*)d_in[1];  // [B,Q,4]
    const float* boxes       = (const float*)d_in[2];  // [B,Q,4]
    const float* area        = (const float*)d_in[3];  // [B,Q]
    const int*   labels      = (const int*)d_in[4];    // [B,Q]
    float* out = (float*)d_out;                        // [B,Q,Q]

    // Softmax: one warp per row, 8 warps per block
    int rows = BB * QQ;                 // 28800 warps
    int blocks = (rows * 32 + 255) / 256;
    softmax_rows_kernel<<<blocks, 256>>>(pred_logits);

    dim3 grid(QQ / TI, BB);             // (45, 32)
    cost_kernel<<<grid, 256>>>(pred_boxes, boxes, area, labels, out);
}

// round 5
// speedup vs baseline: 1.1929x; 1.1929x over previous
#include <cuda_runtime.h>
#include <cstdint>

// Problem constants (fixed by the reference)
#define BB 32
#define QQ 900
#define CC 92
#define BIGV 100000000.0f
#define TI 20          // i-rows per block (900 % 20 == 0 -> 45 blocks in x)
#define J4 (QQ / 4)    // 225 float4 groups per output row

// Scratch: softmax stores (1 - prob) for FFMA folding in the cost kernel.
__device__ float g_nprobs[BB * QQ * CC];

__device__ __forceinline__ float fast_rcp(float x) {
    float r;
    asm("rcp.approx.ftz.f32 %0, %1;" : "=f"(r) : "f"(x));
    return r;
}

// ---------------------------------------------------------------------------
// Kernel 1: row softmax, stores (1 - p). One warp per (b,i) row of 92 logits.
// ---------------------------------------------------------------------------
__global__ void softmax_rows_kernel(const float* __restrict__ logits) {
    int gwarp = (blockIdx.x * blockDim.x + threadIdx.x) >> 5;
    int lane  = threadIdx.x & 31;
    if (gwarp >= BB * QQ) return;

    const float* in = logits + (size_t)gwarp * CC;
    float v0 = in[lane];
    float v1 = in[lane + 32];
    bool has2 = lane < (CC - 64);          // lane < 28
    float v2 = has2 ? in[lane + 64] : -1e30f;

    float m = fmaxf(fmaxf(v0, v1), v2);
    #pragma unroll
    for (int o = 16; o > 0; o >>= 1)
        m = fmaxf(m, __shfl_xor_sync(0xFFFFFFFFu, m, o));

    float e0 = __expf(v0 - m);
    float e1 = __expf(v1 - m);
    float e2 = has2 ? __expf(v2 - m) : 0.0f;
    float s = e0 + e1 + e2;
    #pragma unroll
    for (int o = 16; o > 0; o >>= 1)
        s += __shfl_xor_sync(0xFFFFFFFFu, s, o);

    float inv = __fdividef(1.0f, s);
    float* outp = g_nprobs + (size_t)gwarp * CC;
    outp[lane]      = fmaf(e0, -inv, 1.0f);
    outp[lane + 32] = fmaf(e1, -inv, 1.0f);
    if (has2) outp[lane + 64] = fmaf(e2, -inv, 1.0f);
}

// ---------------------------------------------------------------------------
// Kernel 2: cost matrix. Block = (i-tile of TI rows, batch b).
// Each thread owns 4 consecutive j and emits TI float4 (STG.128) stores.
//   cost = 0.25*L1 + (1 - prob) - inter/uni - uni/enc
//   enc width via exact identity: ew = pw + gw - iw_unclamped (no clamp needed)
// ---------------------------------------------------------------------------
__global__ __launch_bounds__(256)
void cost_kernel(const float* __restrict__ pred_boxes,
                 const float* __restrict__ boxes,
                 const float* __restrict__ area,
                 const int*   __restrict__ labels,
                 float* __restrict__ out) {
    const int b  = blockIdx.y;
    const int i0 = blockIdx.x * TI;
    const int tid = threadIdx.x;

    __shared__ float  s_np[TI][CC];     // (1 - prob) rows for the i-tile
    __shared__ float4 s_c[TI];          // pred box cxcywh
    __shared__ float4 s_x[TI];          // pred box xyxy
    __shared__ float  s_a1[TI];         // pred box area (w*h)

    for (int k = tid; k < TI * CC; k += 256) {
        int ii = k / CC;
        int c  = k - ii * CC;
        s_np[ii][c] = g_nprobs[((size_t)(b * QQ + i0 + ii)) * CC + c];
    }
    if (tid < TI) {
        float4 pb = reinterpret_cast<const float4*>(pred_boxes)[b * QQ + i0 + tid];
        s_c[tid] = pb;
        s_x[tid] = make_float4(pb.x - 0.5f * pb.z, pb.y - 0.5f * pb.w,
                               pb.x + 0.5f * pb.z, pb.y + 0.5f * pb.w);
        s_a1[tid] = pb.z * pb.w;
    }
    __syncthreads();

    if (tid >= J4) return;              // 225 active threads cover j=0..899
    const int j0 = tid * 4;

    float4 gb[4];
    float gx0[4], gy0[4], gx1[4], gy1[4], a2[4];
    bool  valid[4];
    const float* npcol[4];              // &s_np[0][lab[t]]
    #pragma unroll
    for (int t = 0; t < 4; t++) {
        gb[t] = reinterpret_cast<const float4*>(boxes)[b * QQ + j0 + t];
        int lab = labels[b * QQ + j0 + t];
        npcol[t] = &s_np[0][lab];
        valid[t] = area[b * QQ + j0 + t] > 0.0f;
        gx0[t] = gb[t].x - 0.5f * gb[t].z; gy0[t] = gb[t].y - 0.5f * gb[t].w;
        gx1[t] = gb[t].x + 0.5f * gb[t].z; gy1[t] = gb[t].y + 0.5f * gb[t].w;
        a2[t]  = gb[t].z * gb[t].w;
    }

    float* obase = out + ((size_t)(b * QQ + i0)) * QQ + j0;

    #pragma unroll 5
    for (int ii = 0; ii < TI; ii++) {
        float4 pc = s_c[ii];
        float4 px = s_x[ii];
        float  a1 = s_a1[ii];
        float4 res;
        float* r = &res.x;
        #pragma unroll
        for (int t = 0; t < 4; t++) {
            // mean-L1 (x0.25 folded into final FFMA)
            float d0 = pc.x - gb[t].x, d1 = pc.y - gb[t].y;
            float d2 = pc.z - gb[t].z, d3 = pc.w - gb[t].w;
            float L1 = (fabsf(d0) + fabsf(d1)) + (fabsf(d2) + fabsf(d3));

            // intersection (clamped) + enclosing via width identity (exact)
            float iwu = fminf(px.z, gx1[t]) - fmaxf(px.x, gx0[t]);
            float ihu = fminf(px.w, gy1[t]) - fmaxf(px.y, gy0[t]);
            float iw = fmaxf(iwu, 0.0f), ih = fmaxf(ihu, 0.0f);
            float inter = iw * ih;
            float uni = (a1 + a2[t]) - inter;
            float ew = (pc.z + gb[t].z) - iwu;   // = max-min, always >= 0
            float eh = (pc.w + gb[t].w) - ihu;
            float enc = ew * eh;

            float ru = fast_rcp(uni);
            float re = fast_rcp(enc);

            // cost = 0.25*L1 + (1-prob) - inter/uni - uni/enc
            float base = fmaf(L1, 0.25f, npcol[t][ii * CC]);
            base = fmaf(-uni, re, base);
            float cost = fmaf(-inter, ru, base);
            r[t] = valid[t] ? cost : BIGV;
        }
        reinterpret_cast<float4*>(obase + (size_t)ii * QQ)[0] = res;
    }
}

extern "C" void kernel_launch(void* const* d_in, const int* in_sizes, int n_in,
                              void* d_out, int out_size) {
    const float* pred_logits = (const float*)d_in[0];  // [B,Q,C]
    const float* pred_boxes  = (const float*)d_in[1];  // [B,Q,4]
    const float* boxes       = (const float*)d_in[2];  // [B,Q,4]
    const float* area        = (const float*)d_in[3];  // [B,Q]
    const int*   labels      = (const int*)d_in[4];    // [B,Q]
    float* out = (float*)d_out;                        // [B,Q,Q]

    int rows = BB * QQ;                 // 28800 warps
    int blocks = (rows * 32 + 255) / 256;
    softmax_rows_kernel<<<blocks, 256>>>(pred_logits);

    dim3 grid(QQ / TI, BB);             // (45, 32)
    cost_kernel<<<grid, 256>>>(pred_boxes, boxes, area, labels, out);
}